// round 5
// baseline (speedup 1.0000x reference)
#include <cuda_runtime.h>
#include <math.h>

// Fixed problem shapes
#define B_    4
#define N_    10
#define K_    5
#define Q_    512
#define D_    1536
#define D4_   384            // float4 per row

#define QS_   32             // Q chunks per batch
#define QC_   16             // query rows per block
#define NBLK_ 128            // B*QS  (<=148 SMs: single co-resident wave)
#define NT_   768            // 2 halves x 384 columns
#define NW_   (NT_ / 32)     // 24 warps
#define NP2_  (B_ * N_)      // 40 phase-2 blocks

// Scratch (allocation-free)
__device__ float4   g_qsum4[NBLK_ * D4_];   // per-(b,qs) 16-row column sums
__device__ float    g_ss[NBLK_];            // per-(b,qs) sum of squares
__device__ unsigned g_cnt;                  // monotone barrier counter (wrap-safe)

__global__ void __launch_bounds__(NT_, 1)
fused_kernel(const float4* __restrict__ q4,
             const float4* __restrict__ sup4,
             float* __restrict__ out) {
    const int tid  = threadIdx.x;
    const int lane = tid & 31;
    const int wid  = tid >> 5;
    const int bid  = blockIdx.x;
    const int col  = (tid < D4_) ? tid : tid - D4_;   // 0..383
    const int half = (tid >= D4_);                    // 0/1

    __shared__ float4 s_half[D4_];       // cross-half column-sum combine (6 KB)
    __shared__ float4 s_sv[K_ * D4_];    // prefetched support tile (30 KB)
    __shared__ float  s_wred[NW_];
    __shared__ float  s_red[2 * K_ * 12];
    __shared__ float  s_c;
    __shared__ float  s_w[K_];

    const bool is_p2 = (bid < NP2_);

    // ---- phase-2 support prefetch: issue DRAM loads early ----
    float4 sv0, sv1, sv2, sv3, sv4;
    if (is_p2 && tid < D4_) {
        const float4* sp = sup4 + (size_t)bid * K_ * D4_ + col;
        sv0 = sp[0 * D4_]; sv1 = sp[1 * D4_]; sv2 = sp[2 * D4_];
        sv3 = sp[3 * D4_]; sv4 = sp[4 * D4_];
    }

    // ======================= Phase 1: query stats =======================
    {
        const int b  = bid >> 5;
        const int qs = bid & 31;
        // rows: qs*16 + half + 2*i, i=0..7
        const float4* qp = q4 + ((size_t)(b * Q_ + qs * QC_ + half)) * D4_ + col;

        float4 s = make_float4(0.f, 0.f, 0.f, 0.f);
        float ss = 0.f;
        #pragma unroll
        for (int i = 0; i < 8; i++) {
            float4 v = qp[(size_t)(2 * i) * D4_];
            s.x += v.x; s.y += v.y; s.z += v.z; s.w += v.w;
            ss += v.x * v.x + v.y * v.y + v.z * v.z + v.w * v.w;
        }

        if (half) s_half[col] = s;
        __syncthreads();
        if (!half) {
            float4 o = s_half[col];
            s.x += o.x; s.y += o.y; s.z += o.z; s.w += o.w;
            g_qsum4[(size_t)bid * D4_ + col] = s;
        }

        // sum-of-squares over all 24 warps
        #pragma unroll
        for (int off = 16; off > 0; off >>= 1)
            ss += __shfl_down_sync(0xffffffffu, ss, off);
        if (lane == 0) s_wred[wid] = ss;
        __syncthreads();
        if (tid == 0) {
            float t = 0.f;
            #pragma unroll
            for (int w = 0; w < NW_; w++) t += s_wred[w];
            g_ss[bid] = t;
        }

        // stash prefetched support into shared (loads have had time to land)
        if (is_p2 && tid < D4_) {
            s_sv[0 * D4_ + col] = sv0; s_sv[1 * D4_ + col] = sv1;
            s_sv[2 * D4_ + col] = sv2; s_sv[3 * D4_ + col] = sv3;
            s_sv[4 * D4_ + col] = sv4;
        }
    }

    // ======================= Barrier: all arrive, only phase-2 blocks wait ====
    __syncthreads();
    if (tid == 0) {
        __threadfence();                                   // publish qsum/ss
        unsigned old = atomicAdd(&g_cnt, 1u);
        if (is_p2) {
            unsigned target = old - (old & (NBLK_ - 1)) + NBLK_;  // wrap-safe
            while ((int)(*(volatile unsigned*)&g_cnt - target) < 0) { }
            __threadfence();                               // acquire
        }
    }
    if (!is_p2) return;
    __syncthreads();

    // ======================= Phase 2: weights + aggregation ===================
    const int bn = bid;
    const int bb = bn / N_;
    const float invQ = 1.0f / Q_;

    float dot[K_], nrm[K_];
    if (tid < D4_) {
        // qbar for this column (32 L2-resident partials)
        const float4* qsum = g_qsum4 + (size_t)bb * QS_ * D4_ + col;
        float4 qb = make_float4(0.f, 0.f, 0.f, 0.f);
        #pragma unroll
        for (int qs = 0; qs < QS_; qs++) {
            float4 v = qsum[(size_t)qs * D4_];
            qb.x += v.x; qb.y += v.y; qb.z += v.z; qb.w += v.w;
        }
        qb.x *= invQ; qb.y *= invQ; qb.z *= invQ; qb.w *= invQ;

        #pragma unroll
        for (int k = 0; k < K_; k++) {
            float4 sv = s_sv[k * D4_ + col];
            dot[k] = sv.x * qb.x + sv.y * qb.y + sv.z * qb.z + sv.w * qb.w;
            nrm[k] = sv.x * sv.x + sv.y * sv.y + sv.z * sv.z + sv.w * sv.w;
        }
    }

    // c_b = mean_q ||q||^2 (warp 0)
    if (wid == 0) {
        float cv = g_ss[bb * QS_ + lane];
        #pragma unroll
        for (int off = 16; off > 0; off >>= 1)
            cv += __shfl_down_sync(0xffffffffu, cv, off);
        if (lane == 0) s_c = cv * invQ;
    }

    if (tid < D4_) {
        #pragma unroll
        for (int k = 0; k < K_; k++) {
            float dk = dot[k], nk = nrm[k];
            #pragma unroll
            for (int off = 16; off > 0; off >>= 1) {
                dk += __shfl_down_sync(0xffffffffu, dk, off);
                nk += __shfl_down_sync(0xffffffffu, nk, off);
            }
            if (lane == 0) {
                s_red[k * 12 + wid]        = dk;
                s_red[(K_ + k) * 12 + wid] = nk;
            }
        }
    }
    __syncthreads();

    if (tid == 0) {
        float t[K_];
        float m = -1e30f;
        #pragma unroll
        for (int k = 0; k < K_; k++) {
            float dk = 0.f, nk = 0.f;
            #pragma unroll
            for (int w = 0; w < 12; w++) {
                dk += s_red[k * 12 + w];
                nk += s_red[(K_ + k) * 12 + w];
            }
            t[k] = tanhf(-(nk - 2.0f * dk + s_c));
            m = fmaxf(m, t[k]);
        }
        float Z = 0.f;
        #pragma unroll
        for (int k = 0; k < K_; k++) { t[k] = __expf(t[k] - m); Z += t[k]; }
        float invZ = 1.0f / Z;
        #pragma unroll
        for (int k = 0; k < K_; k++) {
            float wk = t[k] * invZ;
            s_w[k] = wk;
            out[(size_t)B_ * N_ * D_ + bn * K_ + k] = wk;   // qgw
        }
    }
    __syncthreads();

    if (tid < D4_) {
        float4 acc = make_float4(0.f, 0.f, 0.f, 0.f);
        #pragma unroll
        for (int k = 0; k < K_; k++) {
            float wk = s_w[k];
            float4 sv = s_sv[k * D4_ + col];
            acc.x += wk * sv.x; acc.y += wk * sv.y;
            acc.z += wk * sv.z; acc.w += wk * sv.w;
        }
        ((float4*)out)[(size_t)bn * D4_ + col] = acc;       // agg
    }
}

extern "C" void kernel_launch(void* const* d_in, const int* in_sizes, int n_in,
                              void* d_out, int out_size) {
    const float4* support = (const float4*)d_in[0];
    const float4* query   = (const float4*)d_in[1];
    float* out = (float*)d_out;

    fused_kernel<<<NBLK_, NT_>>>(query, support, out);
}

// round 6
// speedup vs baseline: 1.0238x; 1.0238x over previous
#include <cuda_runtime.h>
#include <math.h>

// Fixed problem shapes
#define B_    4
#define N_    10
#define K_    5
#define Q_    512
#define D_    1536
#define D4_   384            // float4 per row

#define QS_   32             // Q chunks per batch
#define QC_   16             // query rows per block
#define NBLK_ 128            // B*QS  (<=148 SMs: single co-resident wave)
#define NT_   768            // 2 halves x 384 columns
#define NW_   (NT_ / 32)     // 24 warps
#define NP2_  (B_ * N_)      // 40 phase-2 blocks

// Scratch (allocation-free)
__device__ float4   g_qsum4[NBLK_ * D4_];   // per-(b,qs) 16-row column sums
__device__ float    g_ss[NBLK_];            // per-(b,qs) sum of squares
__device__ unsigned g_cnt;                  // monotone barrier counter (wrap-safe)

__global__ void __launch_bounds__(NT_, 1)
fused_kernel(const float4* __restrict__ q4,
             const float4* __restrict__ sup4,
             float* __restrict__ out) {
    const int tid  = threadIdx.x;
    const int lane = tid & 31;
    const int wid  = tid >> 5;
    const int bid  = blockIdx.x;
    const int col  = (tid < D4_) ? tid : tid - D4_;   // 0..383
    const int half = (tid >= D4_);                    // 0/1

    __shared__ float4 s_half[D4_];       // cross-half column-sum combine (6 KB)
    __shared__ float4 s_sv[K_ * D4_];    // prefetched support tile (30 KB)
    __shared__ float  s_wred[NW_];
    __shared__ float  s_red[2 * K_ * 12];
    __shared__ float  s_c;
    __shared__ float  s_w[K_];

    const bool is_p2 = (bid < NP2_);

    // ---- phase-2 support prefetch: issue DRAM loads early ----
    float4 sv0, sv1, sv2, sv3, sv4;
    if (is_p2 && tid < D4_) {
        const float4* sp = sup4 + (size_t)bid * K_ * D4_ + col;
        sv0 = sp[0 * D4_]; sv1 = sp[1 * D4_]; sv2 = sp[2 * D4_];
        sv3 = sp[3 * D4_]; sv4 = sp[4 * D4_];
    }

    // ======================= Phase 1: query stats =======================
    {
        const int b  = bid >> 5;
        const int qs = bid & 31;
        // rows: qs*16 + half + 2*i, i=0..7
        const float4* qp = q4 + ((size_t)(b * Q_ + qs * QC_ + half)) * D4_ + col;

        float4 s = make_float4(0.f, 0.f, 0.f, 0.f);
        float ss = 0.f;
        #pragma unroll
        for (int i = 0; i < 8; i++) {
            float4 v = qp[(size_t)(2 * i) * D4_];
            s.x += v.x; s.y += v.y; s.z += v.z; s.w += v.w;
            ss += v.x * v.x + v.y * v.y + v.z * v.z + v.w * v.w;
        }

        if (half) s_half[col] = s;
        __syncthreads();
        if (!half) {
            float4 o = s_half[col];
            s.x += o.x; s.y += o.y; s.z += o.z; s.w += o.w;
            g_qsum4[(size_t)bid * D4_ + col] = s;
        }

        // sum-of-squares over all 24 warps
        #pragma unroll
        for (int off = 16; off > 0; off >>= 1)
            ss += __shfl_down_sync(0xffffffffu, ss, off);
        if (lane == 0) s_wred[wid] = ss;
        __syncthreads();
        if (tid == 0) {
            float t = 0.f;
            #pragma unroll
            for (int w = 0; w < NW_; w++) t += s_wred[w];
            g_ss[bid] = t;
        }

        // stash prefetched support into shared (loads have had time to land)
        if (is_p2 && tid < D4_) {
            s_sv[0 * D4_ + col] = sv0; s_sv[1 * D4_ + col] = sv1;
            s_sv[2 * D4_ + col] = sv2; s_sv[3 * D4_ + col] = sv3;
            s_sv[4 * D4_ + col] = sv4;
        }
    }

    // ======================= Barrier: all arrive, only phase-2 blocks wait ====
    __syncthreads();
    if (tid == 0) {
        __threadfence();                                   // publish qsum/ss
        unsigned old = atomicAdd(&g_cnt, 1u);
        if (is_p2) {
            unsigned target = old - (old & (NBLK_ - 1)) + NBLK_;  // wrap-safe
            while ((int)(*(volatile unsigned*)&g_cnt - target) < 0) { }
            __threadfence();                               // acquire
        }
    }
    if (!is_p2) return;
    __syncthreads();

    // ======================= Phase 2: weights + aggregation ===================
    const int bn = bid;
    const int bb = bn / N_;
    const float invQ = 1.0f / Q_;

    float dot[K_], nrm[K_];
    if (tid < D4_) {
        // qbar for this column (32 L2-resident partials)
        const float4* qsum = g_qsum4 + (size_t)bb * QS_ * D4_ + col;
        float4 qb = make_float4(0.f, 0.f, 0.f, 0.f);
        #pragma unroll
        for (int qs = 0; qs < QS_; qs++) {
            float4 v = qsum[(size_t)qs * D4_];
            qb.x += v.x; qb.y += v.y; qb.z += v.z; qb.w += v.w;
        }
        qb.x *= invQ; qb.y *= invQ; qb.z *= invQ; qb.w *= invQ;

        #pragma unroll
        for (int k = 0; k < K_; k++) {
            float4 sv = s_sv[k * D4_ + col];
            dot[k] = sv.x * qb.x + sv.y * qb.y + sv.z * qb.z + sv.w * qb.w;
            nrm[k] = sv.x * sv.x + sv.y * sv.y + sv.z * sv.z + sv.w * sv.w;
        }
    }

    // c_b = mean_q ||q||^2 (warp 0)
    if (wid == 0) {
        float cv = g_ss[bb * QS_ + lane];
        #pragma unroll
        for (int off = 16; off > 0; off >>= 1)
            cv += __shfl_down_sync(0xffffffffu, cv, off);
        if (lane == 0) s_c = cv * invQ;
    }

    if (tid < D4_) {
        #pragma unroll
        for (int k = 0; k < K_; k++) {
            float dk = dot[k], nk = nrm[k];
            #pragma unroll
            for (int off = 16; off > 0; off >>= 1) {
                dk += __shfl_down_sync(0xffffffffu, dk, off);
                nk += __shfl_down_sync(0xffffffffu, nk, off);
            }
            if (lane == 0) {
                s_red[k * 12 + wid]        = dk;
                s_red[(K_ + k) * 12 + wid] = nk;
            }
        }
    }
    __syncthreads();

    if (tid == 0) {
        float t[K_];
        float m = -1e30f;
        #pragma unroll
        for (int k = 0; k < K_; k++) {
            float dk = 0.f, nk = 0.f;
            #pragma unroll
            for (int w = 0; w < 12; w++) {
                dk += s_red[k * 12 + w];
                nk += s_red[(K_ + k) * 12 + w];
            }
            t[k] = tanhf(-(nk - 2.0f * dk + s_c));
            m = fmaxf(m, t[k]);
        }
        float Z = 0.f;
        #pragma unroll
        for (int k = 0; k < K_; k++) { t[k] = __expf(t[k] - m); Z += t[k]; }
        float invZ = 1.0f / Z;
        #pragma unroll
        for (int k = 0; k < K_; k++) {
            float wk = t[k] * invZ;
            s_w[k] = wk;
            out[(size_t)B_ * N_ * D_ + bn * K_ + k] = wk;   // qgw
        }
    }
    __syncthreads();

    if (tid < D4_) {
        float4 acc = make_float4(0.f, 0.f, 0.f, 0.f);
        #pragma unroll
        for (int k = 0; k < K_; k++) {
            float wk = s_w[k];
            float4 sv = s_sv[k * D4_ + col];
            acc.x += wk * sv.x; acc.y += wk * sv.y;
            acc.z += wk * sv.z; acc.w += wk * sv.w;
        }
        ((float4*)out)[(size_t)bn * D4_ + col] = acc;       // agg
    }
}

extern "C" void kernel_launch(void* const* d_in, const int* in_sizes, int n_in,
                              void* d_out, int out_size) {
    const float4* support = (const float4*)d_in[0];
    const float4* query   = (const float4*)d_in[1];
    float* out = (float*)d_out;

    fused_kernel<<<NBLK_, NT_>>>(query, support, out);
}